// round 11
// baseline (speedup 1.0000x reference)
#include <cuda_runtime.h>
#include <cuda_fp16.h>

#define WIN   3072
#define HOP   192
#define NB    8
#define NT    1000
#define NF    128
#define NOISE_LEN ((NT-1)*HOP)   /* 191808 */
#define HALF  (WIN/2)            /* 1536 */
#define NTHREADS 256

#define PHY(i) ((i) + ((i)>>5))
#define SBUF (WIN + (WIN>>5))    /* 3168 */
#define SMEM_BYTES (2*SBUF*(int)sizeof(float2))   /* 50688 */

__device__ float2 g_tw[WIN];      // w3072^j = exp(-2*pi*i*j/3072)
__device__ float  g_hann[WIN];
__device__ __half g_scratch[NB*NT*WIN];   // windowed out_frames, fp16, ~49 MB

// ---------------------------------------------------------------- complex ops
__device__ __forceinline__ float2 cadd(float2 a, float2 b){ return make_float2(a.x+b.x, a.y+b.y); }
__device__ __forceinline__ float2 csub(float2 a, float2 b){ return make_float2(a.x-b.x, a.y-b.y); }
__device__ __forceinline__ float2 cmul(float2 a, float2 b){
    return make_float2(a.x*b.x - a.y*b.y, a.x*b.y + a.y*b.x);
}

// forward DFT-4 (e^{-2pi i jk/4})
__device__ __forceinline__ void dft4(float2 &a0, float2 &a1, float2 &a2, float2 &a3){
    float2 t0 = cadd(a0,a2), t1 = csub(a0,a2);
    float2 t2 = cadd(a1,a3), t3 = csub(a1,a3);
    a0 = cadd(t0,t2);
    a2 = csub(t0,t2);
    a1 = make_float2(t1.x + t3.y, t1.y - t3.x);  // t1 - i*t3
    a3 = make_float2(t1.x - t3.y, t1.y + t3.x);  // t1 + i*t3
}

// forward DFT-3
__device__ __forceinline__ void dft3(float2 &a, float2 &b, float2 &c){
    float2 s = cadd(b,c);
    float2 d = csub(b,c);
    float2 t = make_float2(a.x - 0.5f*s.x, a.y - 0.5f*s.y);
    float ux = 0.8660254037844386f*d.x, uy = 0.8660254037844386f*d.y;
    float2 y0 = cadd(a,s);
    b = make_float2(t.x + uy, t.y - ux);  // t - i*u
    c = make_float2(t.x - uy, t.y + ux);  // t + i*u
    a = y0;
}

// DFT-12, input v[j] with j = r + 4c. After: X[k3 + 3*k1] at v[k1 + 4*k3].
__device__ __forceinline__ void dft12(float2 *v){
    dft3(v[0], v[4], v[8]);
    dft3(v[1], v[5], v[9]);
    dft3(v[2], v[6], v[10]);
    dft3(v[3], v[7], v[11]);
    const float H3 = 0.8660254037844386f;
    v[5]  = cmul(v[5],  make_float2( H3,  -0.5f));   // w12^1
    v[6]  = cmul(v[6],  make_float2( 0.5f, -H3));    // w12^2
    v[7]  = make_float2(v[7].y, -v[7].x);            // w12^3 = -i
    v[9]  = cmul(v[9],  make_float2( 0.5f, -H3));    // w12^2
    v[10] = cmul(v[10], make_float2(-0.5f, -H3));    // w12^4
    v[11] = make_float2(-v[11].x, -v[11].y);         // w12^6 = -1
    dft4(v[0], v[1], v[2],  v[3]);
    dft4(v[4], v[5], v[6],  v[7]);
    dft4(v[8], v[9], v[10], v[11]);
}

// DFT-16, input v[j] with j = r + 4c. After: X[k4 + 4*k1] at v[k1 + 4*k4].
__device__ __forceinline__ void dft16(float2 *v){
    dft4(v[0], v[4], v[8],  v[12]);
    dft4(v[1], v[5], v[9],  v[13]);
    dft4(v[2], v[6], v[10], v[14]);
    dft4(v[3], v[7], v[11], v[15]);
    const float C1 = 0.9238795325112867f;
    const float S1 = 0.3826834323650898f;
    const float R2 = 0.7071067811865476f;
    v[5]  = cmul(v[5],  make_float2( C1, -S1));   // w16^1
    v[6]  = cmul(v[6],  make_float2( R2, -R2));   // w16^2
    v[7]  = cmul(v[7],  make_float2( S1, -C1));   // w16^3
    v[9]  = cmul(v[9],  make_float2( R2, -R2));   // w16^2
    v[10] = make_float2(v[10].y, -v[10].x);       // w16^4 = -i
    v[11] = cmul(v[11], make_float2(-R2, -R2));   // w16^6
    v[13] = cmul(v[13], make_float2( S1, -C1));   // w16^3
    v[14] = cmul(v[14], make_float2(-R2, -R2));   // w16^6
    v[15] = cmul(v[15], make_float2(-C1,  S1));   // w16^9
    dft4(v[0], v[1], v[2],  v[3]);
    dft4(v[4], v[5], v[6],  v[7]);
    dft4(v[8], v[9], v[10], v[11]);
    dft4(v[12],v[13],v[14], v[15]);
}

// radix-16 MIDDLE stage: src -> dst, 192 butterflies (tid = 12*p + q), twiddled
__device__ __forceinline__ void stage16_mid(const float2 *src, float2 *dst, int tid){
    if (tid < 192){
        float2 v[16];
        int q = tid % 12, p = tid / 12;
        #pragma unroll
        for (int i = 0; i < 16; i++) v[i] = src[PHY(tid + 192*i)];
        dft16(v);
        #pragma unroll
        for (int k = 0; k < 16; k++){
            float2 X = v[(k>>2) + 4*(k&3)];
            if (k && p) X = cmul(X, g_tw[12*p*k]);   // w256^{pk}
            dst[PHY(q + 192*p + 12*k)] = X;
        }
    }
    __syncthreads();
}

// radix-16 LAST stage: src -> dst, NO twiddle, output mapping tid + 192*k
__device__ __forceinline__ void stage16_last(const float2 *src, float2 *dst, int tid){
    if (tid < 192){
        float2 v[16];
        #pragma unroll
        for (int i = 0; i < 16; i++) v[i] = src[PHY(tid + 192*i)];
        dft16(v);
        #pragma unroll
        for (int k = 0; k < 16; k++){
            float2 X = v[(k>>2) + 4*(k&3)];
            dst[PHY(tid + 192*k)] = X;
        }
    }
    __syncthreads();
}

// ---------------------------------------------------------------- kernels
__global__ void init_tables(){
    int j = blockIdx.x*blockDim.x + threadIdx.x;
    if (j < WIN){
        float s, c;
        sincospif(-2.0f * (float)j / (float)WIN, &s, &c);
        g_tw[j] = make_float2(c, s);
        float sh = sinpif((float)j / (float)(WIN-1));
        g_hann[j] = sh * sh;   // 0.5 - 0.5*cos(2*pi*j/(N-1))
    }
}

// One block = one PAIR of frames (2t, 2t+1) packed as z = x + i*y.
// Fully fused: gmem->stage1, filter->stage1', stage3'->gmem(fp16). 6 barriers.
__global__ void __launch_bounds__(NTHREADS, 4)
synth_kernel(const float* __restrict__ fb, const float* __restrict__ noise){
    extern __shared__ float2 smem2[];
    float2* Za = smem2;          // buffer A
    float2* Zb = smem2 + SBUF;   // buffer B
    __shared__ float gsx[NF];
    __shared__ float gsy[NF];

    int tp  = blockIdx.x;          // 0..499
    int b   = blockIdx.y;
    int tid = threadIdx.x;
    int t0  = 2*tp;

    // filter gains for frames t0, t0+1 (consumed after >=3 barriers: safe)
    if (tid < NF){
        float2 g2 = *(const float2*)&fb[(b*NF + tid)*NT + t0];
        gsx[tid] = g2.x;
        gsy[tid] = g2.y;
    }

    int base = t0*HOP - HALF;
    const float* nb = noise + b*NOISE_LEN;

    // ======== forward FFT: gmem -> s1 -> Zb -> s2(mid) -> Za -> s3(last) -> Zb
    {
        float2 v[12];
        int p = tid;
        #pragma unroll
        for (int i = 0; i < 12; i++){
            int n  = p + 256*i;
            int i0 = base + n;
            int i1 = i0 + HOP;
            float x = (i0 >= 0 && i0 < NOISE_LEN) ? __ldg(&nb[i0]) : 0.0f;
            float y = (i1 >= 0 && i1 < NOISE_LEN) ? __ldg(&nb[i1]) : 0.0f;
            v[i] = make_float2(x, y);
        }
        dft12(v);
        #pragma unroll
        for (int k = 0; k < 12; k++){
            float2 X = v[(k/3) + 4*(k%3)];
            if (k) X = cmul(X, g_tw[p*k]);
            Zb[PHY(12*p + k)] = X;
        }
        __syncthreads();
    }
    stage16_mid (Zb, Za, tid);   // s2 (twiddled)
    stage16_last(Za, Zb, tid);   // s3 (no twiddle): forward spectrum now in Zb

    // ======== inverse FFT with fused filter:
    //   s1' reads filtered spectrum directly from Zb, writes Za
    {
        float2 v[12];
        int p = tid;
        #pragma unroll
        for (int i = 0; i < 12; i++){
            int n = p + 256*i;
            float2 W;
            if (n == 0){
                W = make_float2(0.0f, 0.0f);                 // H[0] = 0
            } else if (n == HALF){
                float2 A = Zb[PHY(HALF)];                    // Nyquist (X,Y real)
                W = make_float2(gsx[NF-1]*A.x, -gsy[NF-1]*A.y);
            } else {
                int k    = (n < HALF) ? n : (WIN - n);       // 1..1535
                float2 A = Zb[PHY(k)];
                float2 B = Zb[PHY(WIN - k)];
                float Xx = 0.5f*(A.x + B.x), Xy = 0.5f*(A.y - B.y);
                float Yx = 0.5f*(A.y + B.y), Yy = -0.5f*(A.x - B.x);
                int band = (k - 1)/12;
                float hx = gsx[band], hy = gsy[band];
                if (n < HALF){
                    W = make_float2(hx*Xx - hy*Yy, -(hx*Xy + hy*Yx));
                } else {
                    W = make_float2(hx*Xx + hy*Yy, -(-hx*Xy + hy*Yx));
                }
            }
            v[i] = W;
        }
        dft12(v);
        #pragma unroll
        for (int k = 0; k < 12; k++){
            float2 X = v[(k/3) + 4*(k%3)];
            if (k) X = cmul(X, g_tw[p*k]);
            Za[PHY(12*p + k)] = X;
        }
        __syncthreads();
    }
    stage16_mid(Za, Zb, tid);   // s2' (twiddled)

    // s3' (last): Zb -> registers -> windowed, coalesced fp16 STG to scratch
    if (tid < 192){
        float2 v[16];
        #pragma unroll
        for (int i = 0; i < 16; i++) v[i] = Zb[PHY(tid + 192*i)];
        dft16(v);
        const float inv = 1.0f/(float)WIN;
        __half* scx = g_scratch + (size_t)(b*NT + t0)*WIN;
        __half* scy = scx + WIN;
        #pragma unroll
        for (int k = 0; k < 16; k++){
            float2 X = v[(k>>2) + 4*(k&3)];
            int n = tid + 192*k;
            float w = inv * __ldg(&g_hann[n]);
            scx[n] = __float2half_rn( X.x * w);   // frame t0
            scy[n] = __float2half_rn(-X.y * w);   // frame t0+1
        }
    }
}

// 8 consecutive outputs per thread; interior frames contribute one aligned
// 16-byte load (8 halfs). s and all frame offsets are multiples of 8? —
// s % 8 == 0 and HOP=192 % 8 == 0, so (s - HOP*tt) % 8 == 0: aligned.
__global__ void ola_kernel(float* __restrict__ out){
    const int GP = NOISE_LEN/8;            // 23976 groups per batch
    int gid = blockIdx.x*blockDim.x + threadIdx.x;
    if (gid >= NB*GP) return;
    int b = gid / GP;
    int g = gid - b*GP;
    int s = 8*g + HALF;                    // s % 8 == 0
    const __half* base = g_scratch + (size_t)b*NT*WIN;

    int tl0 = (s     >= 2880) ? (s     - 2880)/HOP : 0;   // t_lo for element 0
    int tl7 = (s + 7 >= 2880) ? (s + 7 - 2880)/HOP : 0;   // t_lo for element 7
    int th0 = s/HOP;       if (th0 > NT-1) th0 = NT-1;    // t_hi for element 0
    int th7 = (s + 7)/HOP; if (th7 > NT-1) th7 = NT-1;    // t_hi for element 7

    float acc[8] = {0.f,0.f,0.f,0.f,0.f,0.f,0.f,0.f};
    // frames valid for all 8 elements: one 16-byte load
    for (int tt = tl7; tt <= th0; tt++){
        const uint4 raw = *(const uint4*)&base[tt*WIN + (s - HOP*tt)];
        const __half2* h2 = (const __half2*)&raw;
        #pragma unroll
        for (int j = 0; j < 4; j++){
            float2 f = __half22float2(h2[j]);
            acc[2*j]   += f.x;
            acc[2*j+1] += f.y;
        }
    }
    // low-boundary frame(s): valid only for leading elements (o+j <= 3071)
    for (int tt = tl0; tt < tl7; tt++){
        int o0 = s - HOP*tt;
        #pragma unroll
        for (int j = 0; j < 8; j++)
            if (o0 + j <= WIN-1) acc[j] += __half2float(base[tt*WIN + o0 + j]);
    }
    // high-boundary frame(s): valid only for trailing elements (o+j >= 0)
    for (int tt = th0+1; tt <= th7; tt++){
        int o0 = s - HOP*tt;
        #pragma unroll
        for (int j = 0; j < 8; j++)
            if (o0 + j >= 0) acc[j] += __half2float(base[tt*WIN + o0 + j]);
    }
    float4* po = (float4*)&out[b*NOISE_LEN + 8*g];
    po[0] = make_float4(acc[0], acc[1], acc[2], acc[3]);
    po[1] = make_float4(acc[4], acc[5], acc[6], acc[7]);
}

// ---------------------------------------------------------------- launch
extern "C" void kernel_launch(void* const* d_in, const int* in_sizes, int n_in,
                              void* d_out, int out_size){
    const float* fb    = (const float*)d_in[0];
    const float* noise = (const float*)d_in[1];
    if (n_in >= 2 && in_sizes[0] == NB*NOISE_LEN && in_sizes[1] == NB*NF*NT){
        const float* tmp = fb; fb = noise; noise = tmp;
    }
    float* out = (float*)d_out;

    cudaFuncSetAttribute(synth_kernel,
                         cudaFuncAttributeMaxDynamicSharedMemorySize, SMEM_BYTES);

    init_tables<<<(WIN + 255)/256, 256>>>();
    dim3 grid(NT/2, NB);
    synth_kernel<<<grid, NTHREADS, SMEM_BYTES>>>(fb, noise);
    int n_groups = NB*(NOISE_LEN/8);
    ola_kernel<<<(n_groups + 255)/256, 256>>>(out);
}

// round 12
// speedup vs baseline: 1.0502x; 1.0502x over previous
#include <cuda_runtime.h>
#include <cuda_fp16.h>

#define WIN   3072
#define HOP   192
#define NB    8
#define NT    1000
#define NF    128
#define NOISE_LEN ((NT-1)*HOP)   /* 191808 */
#define HALF  (WIN/2)            /* 1536 */
#define NTHREADS 256

#define PHY(i) ((i) + ((i)>>5))
#define SBUF (WIN + (WIN>>5))    /* 3168 */
#define SMEM_BYTES (2*SBUF*(int)sizeof(float2))   /* 50688 */

__device__ float2 g_tw[WIN];      // w3072^j = exp(-2*pi*i*j/3072)
__device__ float  g_hann[WIN];
__device__ __half g_scratch[NB*NT*WIN];   // windowed out_frames, fp16, ~49 MB

// ---------------------------------------------------------------- complex ops
__device__ __forceinline__ float2 cadd(float2 a, float2 b){ return make_float2(a.x+b.x, a.y+b.y); }
__device__ __forceinline__ float2 csub(float2 a, float2 b){ return make_float2(a.x-b.x, a.y-b.y); }
__device__ __forceinline__ float2 cmul(float2 a, float2 b){
    return make_float2(a.x*b.x - a.y*b.y, a.x*b.y + a.y*b.x);
}

// forward DFT-4 (e^{-2pi i jk/4})
__device__ __forceinline__ void dft4(float2 &a0, float2 &a1, float2 &a2, float2 &a3){
    float2 t0 = cadd(a0,a2), t1 = csub(a0,a2);
    float2 t2 = cadd(a1,a3), t3 = csub(a1,a3);
    a0 = cadd(t0,t2);
    a2 = csub(t0,t2);
    a1 = make_float2(t1.x + t3.y, t1.y - t3.x);  // t1 - i*t3
    a3 = make_float2(t1.x - t3.y, t1.y + t3.x);  // t1 + i*t3
}

// forward DFT-3
__device__ __forceinline__ void dft3(float2 &a, float2 &b, float2 &c){
    float2 s = cadd(b,c);
    float2 d = csub(b,c);
    float2 t = make_float2(a.x - 0.5f*s.x, a.y - 0.5f*s.y);
    float ux = 0.8660254037844386f*d.x, uy = 0.8660254037844386f*d.y;
    float2 y0 = cadd(a,s);
    b = make_float2(t.x + uy, t.y - ux);  // t - i*u
    c = make_float2(t.x - uy, t.y + ux);  // t + i*u
    a = y0;
}

// DFT-12, input v[j] with j = r + 4c. After: X[k3 + 3*k1] at v[k1 + 4*k3].
__device__ __forceinline__ void dft12(float2 *v){
    dft3(v[0], v[4], v[8]);
    dft3(v[1], v[5], v[9]);
    dft3(v[2], v[6], v[10]);
    dft3(v[3], v[7], v[11]);
    const float H3 = 0.8660254037844386f;
    v[5]  = cmul(v[5],  make_float2( H3,  -0.5f));   // w12^1
    v[6]  = cmul(v[6],  make_float2( 0.5f, -H3));    // w12^2
    v[7]  = make_float2(v[7].y, -v[7].x);            // w12^3 = -i
    v[9]  = cmul(v[9],  make_float2( 0.5f, -H3));    // w12^2
    v[10] = cmul(v[10], make_float2(-0.5f, -H3));    // w12^4
    v[11] = make_float2(-v[11].x, -v[11].y);         // w12^6 = -1
    dft4(v[0], v[1], v[2],  v[3]);
    dft4(v[4], v[5], v[6],  v[7]);
    dft4(v[8], v[9], v[10], v[11]);
}

// DFT-16, input v[j] with j = r + 4c. After: X[k4 + 4*k1] at v[k1 + 4*k4].
__device__ __forceinline__ void dft16(float2 *v){
    dft4(v[0], v[4], v[8],  v[12]);
    dft4(v[1], v[5], v[9],  v[13]);
    dft4(v[2], v[6], v[10], v[14]);
    dft4(v[3], v[7], v[11], v[15]);
    const float C1 = 0.9238795325112867f;
    const float S1 = 0.3826834323650898f;
    const float R2 = 0.7071067811865476f;
    v[5]  = cmul(v[5],  make_float2( C1, -S1));   // w16^1
    v[6]  = cmul(v[6],  make_float2( R2, -R2));   // w16^2
    v[7]  = cmul(v[7],  make_float2( S1, -C1));   // w16^3
    v[9]  = cmul(v[9],  make_float2( R2, -R2));   // w16^2
    v[10] = make_float2(v[10].y, -v[10].x);       // w16^4 = -i
    v[11] = cmul(v[11], make_float2(-R2, -R2));   // w16^6
    v[13] = cmul(v[13], make_float2( S1, -C1));   // w16^3
    v[14] = cmul(v[14], make_float2(-R2, -R2));   // w16^6
    v[15] = cmul(v[15], make_float2(-C1,  S1));   // w16^9
    dft4(v[0], v[1], v[2],  v[3]);
    dft4(v[4], v[5], v[6],  v[7]);
    dft4(v[8], v[9], v[10], v[11]);
    dft4(v[12],v[13],v[14], v[15]);
}

// radix-16 MIDDLE stage: src -> dst, 192 butterflies (tid = 12*p + q), twiddled
__device__ __forceinline__ void stage16_mid(const float2 *src, float2 *dst, int tid){
    if (tid < 192){
        float2 v[16];
        int q = tid % 12, p = tid / 12;
        #pragma unroll
        for (int i = 0; i < 16; i++) v[i] = src[PHY(tid + 192*i)];
        dft16(v);
        #pragma unroll
        for (int k = 0; k < 16; k++){
            float2 X = v[(k>>2) + 4*(k&3)];
            if (k && p) X = cmul(X, g_tw[12*p*k]);   // w256^{pk}
            dst[PHY(q + 192*p + 12*k)] = X;
        }
    }
    __syncthreads();
}

// radix-16 LAST stage: src -> dst, NO twiddle, output mapping tid + 192*k
__device__ __forceinline__ void stage16_last(const float2 *src, float2 *dst, int tid){
    if (tid < 192){
        float2 v[16];
        #pragma unroll
        for (int i = 0; i < 16; i++) v[i] = src[PHY(tid + 192*i)];
        dft16(v);
        #pragma unroll
        for (int k = 0; k < 16; k++){
            float2 X = v[(k>>2) + 4*(k&3)];
            dst[PHY(tid + 192*k)] = X;
        }
    }
    __syncthreads();
}

// ---------------------------------------------------------------- kernels
__global__ void init_tables(){
    int j = blockIdx.x*blockDim.x + threadIdx.x;
    if (j < WIN){
        float s, c;
        sincospif(-2.0f * (float)j / (float)WIN, &s, &c);
        g_tw[j] = make_float2(c, s);
        float sh = sinpif((float)j / (float)(WIN-1));
        g_hann[j] = sh * sh;   // 0.5 - 0.5*cos(2*pi*j/(N-1))
    }
}

// One block = one PAIR of frames (2t, 2t+1) packed as z = x + i*y.
// Fully fused: gmem->stage1, filter->stage1', stage3'->gmem(fp16). 6 barriers.
__global__ void __launch_bounds__(NTHREADS, 3)
synth_kernel(const float* __restrict__ fb, const float* __restrict__ noise){
    extern __shared__ float2 smem2[];
    float2* Za = smem2;          // buffer A
    float2* Zb = smem2 + SBUF;   // buffer B
    __shared__ float gsx[NF];
    __shared__ float gsy[NF];

    int tp  = blockIdx.x;          // 0..499
    int b   = blockIdx.y;
    int tid = threadIdx.x;
    int t0  = 2*tp;

    // filter gains for frames t0, t0+1 (consumed after >=3 barriers: safe)
    if (tid < NF){
        float2 g2 = *(const float2*)&fb[(b*NF + tid)*NT + t0];
        gsx[tid] = g2.x;
        gsy[tid] = g2.y;
    }

    int base = t0*HOP - HALF;
    const float* nb = noise + b*NOISE_LEN;

    // ======== forward FFT: gmem -> s1 -> Zb -> s2(mid) -> Za -> s3(last) -> Zb
    {
        float2 v[12];
        int p = tid;
        #pragma unroll
        for (int i = 0; i < 12; i++){
            int n  = p + 256*i;
            int i0 = base + n;
            int i1 = i0 + HOP;
            float x = (i0 >= 0 && i0 < NOISE_LEN) ? __ldg(&nb[i0]) : 0.0f;
            float y = (i1 >= 0 && i1 < NOISE_LEN) ? __ldg(&nb[i1]) : 0.0f;
            v[i] = make_float2(x, y);
        }
        dft12(v);
        #pragma unroll
        for (int k = 0; k < 12; k++){
            float2 X = v[(k/3) + 4*(k%3)];
            if (k) X = cmul(X, g_tw[p*k]);
            Zb[PHY(12*p + k)] = X;
        }
        __syncthreads();
    }
    stage16_mid (Zb, Za, tid);   // s2 (twiddled)
    stage16_last(Za, Zb, tid);   // s3 (no twiddle): forward spectrum now in Zb

    // ======== inverse FFT with fused filter:
    //   s1' reads filtered spectrum directly from Zb, writes Za
    {
        float2 v[12];
        int p = tid;
        #pragma unroll
        for (int i = 0; i < 12; i++){
            int n = p + 256*i;
            float2 W;
            if (n == 0){
                W = make_float2(0.0f, 0.0f);                 // H[0] = 0
            } else if (n == HALF){
                float2 A = Zb[PHY(HALF)];                    // Nyquist (X,Y real)
                W = make_float2(gsx[NF-1]*A.x, -gsy[NF-1]*A.y);
            } else {
                int k    = (n < HALF) ? n : (WIN - n);       // 1..1535
                float2 A = Zb[PHY(k)];
                float2 B = Zb[PHY(WIN - k)];
                float Xx = 0.5f*(A.x + B.x), Xy = 0.5f*(A.y - B.y);
                float Yx = 0.5f*(A.y + B.y), Yy = -0.5f*(A.x - B.x);
                int band = (k - 1)/12;
                float hx = gsx[band], hy = gsy[band];
                if (n < HALF){
                    W = make_float2(hx*Xx - hy*Yy, -(hx*Xy + hy*Yx));
                } else {
                    W = make_float2(hx*Xx + hy*Yy, -(-hx*Xy + hy*Yx));
                }
            }
            v[i] = W;
        }
        dft12(v);
        #pragma unroll
        for (int k = 0; k < 12; k++){
            float2 X = v[(k/3) + 4*(k%3)];
            if (k) X = cmul(X, g_tw[p*k]);
            Za[PHY(12*p + k)] = X;
        }
        __syncthreads();
    }
    stage16_mid(Za, Zb, tid);   // s2' (twiddled)

    // s3' (last): Zb -> registers -> windowed, coalesced fp16 STG to scratch
    if (tid < 192){
        float2 v[16];
        #pragma unroll
        for (int i = 0; i < 16; i++) v[i] = Zb[PHY(tid + 192*i)];
        dft16(v);
        const float inv = 1.0f/(float)WIN;
        __half* scx = g_scratch + (size_t)(b*NT + t0)*WIN;
        __half* scy = scx + WIN;
        #pragma unroll
        for (int k = 0; k < 16; k++){
            float2 X = v[(k>>2) + 4*(k&3)];
            int n = tid + 192*k;
            float w = inv * __ldg(&g_hann[n]);
            scx[n] = __float2half_rn( X.x * w);   // frame t0
            scy[n] = __float2half_rn(-X.y * w);   // frame t0+1
        }
    }
}

// 8 consecutive outputs per thread; interior frames contribute one aligned
// 16-byte load (8 halfs). s % 8 == 0 and HOP % 8 == 0, so offsets stay aligned.
__global__ void ola_kernel(float* __restrict__ out){
    const int GP = NOISE_LEN/8;            // 23976 groups per batch
    int gid = blockIdx.x*blockDim.x + threadIdx.x;
    if (gid >= NB*GP) return;
    int b = gid / GP;
    int g = gid - b*GP;
    int s = 8*g + HALF;                    // s % 8 == 0
    const __half* base = g_scratch + (size_t)b*NT*WIN;

    int tl0 = (s     >= 2880) ? (s     - 2880)/HOP : 0;   // t_lo for element 0
    int tl7 = (s + 7 >= 2880) ? (s + 7 - 2880)/HOP : 0;   // t_lo for element 7
    int th0 = s/HOP;       if (th0 > NT-1) th0 = NT-1;    // t_hi for element 0
    int th7 = (s + 7)/HOP; if (th7 > NT-1) th7 = NT-1;    // t_hi for element 7

    float acc[8] = {0.f,0.f,0.f,0.f,0.f,0.f,0.f,0.f};
    // frames valid for all 8 elements: one 16-byte load
    for (int tt = tl7; tt <= th0; tt++){
        const uint4 raw = *(const uint4*)&base[tt*WIN + (s - HOP*tt)];
        const __half2* h2 = (const __half2*)&raw;
        #pragma unroll
        for (int j = 0; j < 4; j++){
            float2 f = __half22float2(h2[j]);
            acc[2*j]   += f.x;
            acc[2*j+1] += f.y;
        }
    }
    // low-boundary frame(s): valid only for leading elements (o+j <= 3071)
    for (int tt = tl0; tt < tl7; tt++){
        int o0 = s - HOP*tt;
        #pragma unroll
        for (int j = 0; j < 8; j++)
            if (o0 + j <= WIN-1) acc[j] += __half2float(base[tt*WIN + o0 + j]);
    }
    // high-boundary frame(s): valid only for trailing elements (o+j >= 0)
    for (int tt = th0+1; tt <= th7; tt++){
        int o0 = s - HOP*tt;
        #pragma unroll
        for (int j = 0; j < 8; j++)
            if (o0 + j >= 0) acc[j] += __half2float(base[tt*WIN + o0 + j]);
    }
    float4* po = (float4*)&out[b*NOISE_LEN + 8*g];
    po[0] = make_float4(acc[0], acc[1], acc[2], acc[3]);
    po[1] = make_float4(acc[4], acc[5], acc[6], acc[7]);
}

// ---------------------------------------------------------------- launch
extern "C" void kernel_launch(void* const* d_in, const int* in_sizes, int n_in,
                              void* d_out, int out_size){
    const float* fb    = (const float*)d_in[0];
    const float* noise = (const float*)d_in[1];
    if (n_in >= 2 && in_sizes[0] == NB*NOISE_LEN && in_sizes[1] == NB*NF*NT){
        const float* tmp = fb; fb = noise; noise = tmp;
    }
    float* out = (float*)d_out;

    cudaFuncSetAttribute(synth_kernel,
                         cudaFuncAttributeMaxDynamicSharedMemorySize, SMEM_BYTES);

    init_tables<<<(WIN + 255)/256, 256>>>();
    dim3 grid(NT/2, NB);
    synth_kernel<<<grid, NTHREADS, SMEM_BYTES>>>(fb, noise);
    int n_groups = NB*(NOISE_LEN/8);
    ola_kernel<<<(n_groups + 255)/256, 256>>>(out);
}